// round 4
// baseline (speedup 1.0000x reference)
#include <cuda_runtime.h>

#define HDIM 256
#define BM   64
#define BC   256
#define KC   32
#define TPB  256
#define NMAX 8192
#define KMAX 8192

__device__ float g_csq[KMAX];
__device__ float g_hsq[NMAX];
__device__ int   g_idx[NMAX];

__device__ __forceinline__ int csw(int k, int c) { return k * BC + (c ^ (k & 28)); }

__device__ __forceinline__ unsigned long long pack2(float a) {
    unsigned long long r;
    asm("mov.b64 %0, {%1, %1};" : "=l"(r) : "f"(a));
    return r;
}
__device__ __forceinline__ void unpack2(unsigned long long v, float& lo, float& hi) {
    asm("mov.b64 {%0, %1}, %2;" : "=f"(lo), "=f"(hi) : "l"(v));
}
__device__ __forceinline__ void ffma2(unsigned long long& d, unsigned long long a,
                                      unsigned long long b) {
    asm("fma.rn.f32x2 %0, %1, %2, %0;" : "+l"(d) : "l"(a), "l"(b));
}

// k0: squared row norms of h (-> g_hsq) and codebook (-> g_csq), one warp per row
__global__ void sqnorm_kernel(const float* __restrict__ h,
                              const float* __restrict__ cb, int n) {
    int row  = blockIdx.x * 8 + (threadIdx.x >> 5);
    int lane = threadIdx.x & 31;
    const float* src; float* dst;
    if (row < n) { src = h  + (size_t)row * HDIM;       dst = g_hsq + row; }
    else         { src = cb + (size_t)(row - n) * HDIM; dst = g_csq + (row - n); }
    const float4* p = (const float4*)src;
    float s = 0.f;
#pragma unroll
    for (int i = 0; i < 2; i++) {
        float4 v = p[lane + 32 * i];
        s += v.x * v.x + v.y * v.y + v.z * v.z + v.w * v.w;
    }
#pragma unroll
    for (int o = 16; o; o >>= 1) s += __shfl_xor_sync(0xffffffffu, s, o);
    if (lane == 0) *dst = s;
}

// k1: fused dot-product GEMM + per-row argmin
__global__ void __launch_bounds__(TPB, 1)
vq_main_kernel(const float* __restrict__ hin, const float* __restrict__ cb, int ntiles) {
    extern __shared__ float smem[];
    float* hs = smem;               // [HDIM][BM] transposed h tile
    float* cs = smem + HDIM * BM;   // [KC][BC] swizzled code tile

    const int tid = threadIdx.x;
    const int tx  = tid & 31;
    const int ty  = tid >> 5;
    const int rb  = blockIdx.x * BM;

    for (int it = tid; it < BM * (HDIM / 4); it += TPB) {
        int row = it & (BM - 1);
        int kq  = it >> 6;
        float4 v = *(const float4*)(hin + (size_t)(rb + row) * HDIM + kq * 4);
        hs[(kq * 4 + 0) * BM + row] = v.x;
        hs[(kq * 4 + 1) * BM + row] = v.y;
        hs[(kq * 4 + 2) * BM + row] = v.z;
        hs[(kq * 4 + 3) * BM + row] = v.w;
    }

    float hsq[8];
#pragma unroll
    for (int i = 0; i < 8; i++) hsq[i] = g_hsq[rb + ty * 8 + i];

    float minv[8]; int mini[8];
#pragma unroll
    for (int i = 0; i < 8; i++) { minv[i] = 3.4e38f; mini[i] = 0x7fffffff; }

    float4 pf[8];
#pragma unroll
    for (int j = 0; j < 8; j++) {
        int u = tid + j * TPB;
        pf[j] = *(const float4*)(cb + (size_t)(u >> 3) * HDIM + (u & 7) * 4);
    }

    for (int tile = 0; tile < ntiles; tile++) {
        unsigned long long acc[8][4];
#pragma unroll
        for (int i = 0; i < 8; i++)
#pragma unroll
            for (int p = 0; p < 4; p++) acc[i][p] = 0ULL;

#pragma unroll 1
        for (int kc = 0; kc < 8; kc++) {
            __syncthreads();
#pragma unroll
            for (int j = 0; j < 8; j++) {
                int u  = tid + j * TPB;
                int c  = u >> 3;
                int k0 = (u & 7) * 4;
                cs[csw(k0 + 0, c)] = pf[j].x;
                cs[csw(k0 + 1, c)] = pf[j].y;
                cs[csw(k0 + 2, c)] = pf[j].z;
                cs[csw(k0 + 3, c)] = pf[j].w;
            }
            __syncthreads();

            int nkc = kc + 1, ntile = tile;
            if (nkc == 8) { nkc = 0; ntile++; }
            if (ntile < ntiles) {
                const float* base = cb + ((size_t)ntile * BC) * HDIM + nkc * KC;
#pragma unroll
                for (int j = 0; j < 8; j++) {
                    int u = tid + j * TPB;
                    pf[j] = *(const float4*)(base + (size_t)(u >> 3) * HDIM + (u & 7) * 4);
                }
            }

            const float* hb = hs + (kc * KC) * BM + ty * 8;
#pragma unroll 8
            for (int kk = 0; kk < KC; kk++) {
                float4 a0 = *(const float4*)(hb + kk * BM);
                float4 a1 = *(const float4*)(hb + kk * BM + 4);
                const float* bp = cs + kk * BC;
                int sw = (4 * tx) ^ (kk & 28);
                ulonglong2 b0 = *(const ulonglong2*)(bp + sw);
                ulonglong2 b1 = *(const ulonglong2*)(bp + 128 + sw);
                unsigned long long pa;
                pa = pack2(a0.x);
                ffma2(acc[0][0], pa, b0.x); ffma2(acc[0][1], pa, b0.y);
                ffma2(acc[0][2], pa, b1.x); ffma2(acc[0][3], pa, b1.y);
                pa = pack2(a0.y);
                ffma2(acc[1][0], pa, b0.x); ffma2(acc[1][1], pa, b0.y);
                ffma2(acc[1][2], pa, b1.x); ffma2(acc[1][3], pa, b1.y);
                pa = pack2(a0.z);
                ffma2(acc[2][0], pa, b0.x); ffma2(acc[2][1], pa, b0.y);
                ffma2(acc[2][2], pa, b1.x); ffma2(acc[2][3], pa, b1.y);
                pa = pack2(a0.w);
                ffma2(acc[3][0], pa, b0.x); ffma2(acc[3][1], pa, b0.y);
                ffma2(acc[3][2], pa, b1.x); ffma2(acc[3][3], pa, b1.y);
                pa = pack2(a1.x);
                ffma2(acc[4][0], pa, b0.x); ffma2(acc[4][1], pa, b0.y);
                ffma2(acc[4][2], pa, b1.x); ffma2(acc[4][3], pa, b1.y);
                pa = pack2(a1.y);
                ffma2(acc[5][0], pa, b0.x); ffma2(acc[5][1], pa, b0.y);
                ffma2(acc[5][2], pa, b1.x); ffma2(acc[5][3], pa, b1.y);
                pa = pack2(a1.z);
                ffma2(acc[6][0], pa, b0.x); ffma2(acc[6][1], pa, b0.y);
                ffma2(acc[6][2], pa, b1.x); ffma2(acc[6][3], pa, b1.y);
                pa = pack2(a1.w);
                ffma2(acc[7][0], pa, b0.x); ffma2(acc[7][1], pa, b0.y);
                ffma2(acc[7][2], pa, b1.x); ffma2(acc[7][3], pa, b1.y);
            }
        }

        int cbase = tile * BC + 4 * tx;
#pragma unroll
        for (int p = 0; p < 4; p++) {
            int c0 = cbase + (p < 2 ? 2 * p : 128 + 2 * (p - 2));
            float cs0 = __ldg(&g_csq[c0]);
            float cs1 = __ldg(&g_csq[c0 + 1]);
#pragma unroll
            for (int i = 0; i < 8; i++) {
                float d0, d1;
                unpack2(acc[i][p], d0, d1);
                float v0 = __fadd_rn(__fsub_rn(hsq[i], 2.0f * d0), cs0);
                float v1 = __fadd_rn(__fsub_rn(hsq[i], 2.0f * d1), cs1);
                if (v0 < minv[i]) { minv[i] = v0; mini[i] = c0; }
                if (v1 < minv[i]) { minv[i] = v1; mini[i] = c0 + 1; }
            }
        }
    }

#pragma unroll
    for (int i = 0; i < 8; i++) {
        float v = minv[i]; int id = mini[i];
#pragma unroll
        for (int o = 16; o; o >>= 1) {
            float ov = __shfl_xor_sync(0xffffffffu, v, o);
            int   oi = __shfl_xor_sync(0xffffffffu, id, o);
            if (ov < v || (ov == v && oi < id)) { v = ov; id = oi; }
        }
        if (tx == 0) g_idx[rb + ty * 8 + i] = id;
    }
}

// k2: zero + one-hot scatter, one block per row
__global__ void fill_kernel(float* __restrict__ out, int K) {
    int row = blockIdx.x;
    int idx = g_idx[row];
    float4* o = (float4*)(out + (size_t)row * K);
    int nf4 = K >> 2;
    for (int u = threadIdx.x; u < nf4; u += blockDim.x) {
        int c = u << 2;
        float4 v;
        v.x = (c     == idx) ? 1.f : 0.f;
        v.y = (c + 1 == idx) ? 1.f : 0.f;
        v.z = (c + 2 == idx) ? 1.f : 0.f;
        v.w = (c + 3 == idx) ? 1.f : 0.f;
        o[u] = v;
    }
}

// k3: loss = 1.25 * mean((h - z_q)^2), one warp per row
__global__ void loss_kernel(const float* __restrict__ h, const float* __restrict__ cb,
                            float* __restrict__ loss_out) {
    int row  = blockIdx.x * 8 + (threadIdx.x >> 5);
    int lane = threadIdx.x & 31;
    int idx  = g_idx[row];
    const float4* hp = (const float4*)(h  + (size_t)row * HDIM);
    const float4* cp = (const float4*)(cb + (size_t)idx * HDIM);
    float s = 0.f;
#pragma unroll
    for (int i = 0; i < 2; i++) {
        float4 a = hp[lane + 32 * i];
        float4 b = cp[lane + 32 * i];
        float dx = a.x - b.x, dy = a.y - b.y, dz = a.z - b.z, dw = a.w - b.w;
        s += dx * dx + dy * dy + dz * dz + dw * dw;
    }
#pragma unroll
    for (int o = 16; o; o >>= 1) s += __shfl_xor_sync(0xffffffffu, s, o);
    if (lane == 0) loss_out[row] = s * (1.25f / 256.0f);
}

extern "C" void kernel_launch(void* const* d_in, const int* in_sizes, int n_in,
                              void* d_out, int out_size) {
    const float* h  = (const float*)d_in[0];
    const float* cb = (const float*)d_in[2];   // d_in[1] = temperature (unused)
    float* out = (float*)d_out;

    int N = in_sizes[0] / HDIM;
    int K = in_sizes[2] / HDIM;

    int smem_bytes = (HDIM * BM + KC * BC) * 4;   // 96 KB
    static int attr_done = 0;
    if (!attr_done) {
        cudaFuncSetAttribute(vq_main_kernel,
                             cudaFuncAttributeMaxDynamicSharedMemorySize, smem_bytes);
        attr_done = 1;
    }

    sqnorm_kernel<<<(N + K) / 8, 256>>>(h, cb, N);
    vq_main_kernel<<<N / BM, TPB, smem_bytes>>>(h, cb, K / BC);
    fill_kernel<<<N, 256>>>(out, K);
    loss_kernel<<<N / 8, 256>>>(h, cb, out + (size_t)N * K);
}

// round 10
// speedup vs baseline: 1.6265x; 1.6265x over previous
#include <cuda_runtime.h>
#include <cuda_fp16.h>
#include <cstdint>

#define NROWS 8192
#define KCODES 8192
#define HD 256
#define KP 1024          // expanded K: 4 fp16 segments of 256
#define MT 128           // rows per CTA
#define NTT 128          // codes per CTA
#define KCH 128          // fp16 per K chunk (256 B/row)
#define NCH 8            // 1024/128
#define TPB 256

// smem offsets (bytes)
#define SA0 0
#define SB0 32768
#define SA1 65536
#define SB1 98304
#define SRED 131072
#define SMEMSZ 132096

__device__ __align__(128) __half g_HA[(size_t)NROWS * KP];
__device__ __align__(128) __half g_CBH[(size_t)KCODES * KP];
__device__ float g_hsq[NROWS];
__device__ float g_csq[KCODES];
__device__ unsigned long long g_best[NROWS];

__device__ __forceinline__ uint32_t smem_u32(const void* p) {
    uint32_t a;
    asm("{ .reg .u64 t; cvta.to.shared.u64 t, %1; cvt.u32.u64 %0, t; }"
        : "=r"(a) : "l"(p));
    return a;
}
__device__ __forceinline__ void cp16(uint32_t dst, const void* src) {
    asm volatile("cp.async.cg.shared.global [%0], [%1], 16;"
                 :: "r"(dst), "l"(src) : "memory");
}
__device__ __forceinline__ void cp_commit() {
    asm volatile("cp.async.commit_group;" ::: "memory");
}
__device__ __forceinline__ void ldsm4(uint32_t* r, uint32_t a) {
    asm volatile("ldmatrix.sync.aligned.m8n8.x4.shared.b16 {%0,%1,%2,%3}, [%4];"
                 : "=r"(r[0]), "=r"(r[1]), "=r"(r[2]), "=r"(r[3]) : "r"(a));
}
__device__ __forceinline__ void mma16816(float* c, const uint32_t* a, const uint32_t* b) {
    asm volatile("mma.sync.aligned.m16n8k16.row.col.f32.f16.f16.f32 "
                 "{%0,%1,%2,%3}, {%4,%5,%6,%7}, {%8,%9}, {%0,%1,%2,%3};"
                 : "+f"(c[0]), "+f"(c[1]), "+f"(c[2]), "+f"(c[3])
                 : "r"(a[0]), "r"(a[1]), "r"(a[2]), "r"(a[3]), "r"(b[0]), "r"(b[1]));
}

// k0: 2-term fp16 split planes  HA=[h0,h0,h1,h1]  CBH=[c0,c1,c0,c1]
__global__ void prep_kernel(const float* __restrict__ h, const float* __restrict__ cb) {
    size_t i = (size_t)blockIdx.x * TPB + threadIdx.x;
    int which = i >= (size_t)NROWS * HD;
    size_t e = which ? i - (size_t)NROWS * HD : i;
    float x = which ? cb[e] : h[e];
    __half x0 = __float2half_rn(x);
    __half x1 = __float2half_rn(x - __half2float(x0));
    size_t base = (e >> 8) * KP + (e & 255);
    if (!which) {
        g_HA[base] = x0; g_HA[base + 256] = x0;
        g_HA[base + 512] = x1; g_HA[base + 768] = x1;
    } else {
        g_CBH[base] = x0; g_CBH[base + 256] = x1;
        g_CBH[base + 512] = x0; g_CBH[base + 768] = x1;
    }
}

// k1: squared row norms + init g_best
__global__ void sqnorm_kernel(const float* __restrict__ h,
                              const float* __restrict__ cb, int n) {
    int row  = blockIdx.x * 8 + (threadIdx.x >> 5);
    int lane = threadIdx.x & 31;
    const float* src; float* dst;
    if (row < n) { src = h  + (size_t)row * HD;       dst = g_hsq + row;
                   if (lane == 1) g_best[row] = ~0ULL; }
    else         { src = cb + (size_t)(row - n) * HD; dst = g_csq + (row - n); }
    const float4* p = (const float4*)src;
    float s = 0.f;
#pragma unroll
    for (int i = 0; i < 2; i++) {
        float4 v = p[lane + 32 * i];
        s += v.x * v.x + v.y * v.y + v.z * v.z + v.w * v.w;
    }
#pragma unroll
    for (int o = 16; o; o >>= 1) s += __shfl_xor_sync(0xffffffffu, s, o);
    if (lane == 0) *dst = s;
}

// k2: fp16 HMMA GEMM (K=1024) + fused dist/argmin epilogue
__global__ void __launch_bounds__(TPB, 1) vq_mma_kernel() {
    extern __shared__ char smem[];
    const uint32_t sb = smem_u32(smem);
    unsigned long long* sred = (unsigned long long*)(smem + SRED);

    const int tid  = threadIdx.x;
    const int wid  = tid >> 5;
    const int lane = tid & 31;

    if (tid < MT) sred[tid] = ~0ULL;

    // panel-swizzled tile coords: 512 CTAs per 8-wide n panel
    const int bid   = blockIdx.x;
    const int panel = bid >> 9;
    const int mtile = (bid >> 3) & 63;
    const int ntile = (panel << 3) | (bid & 7);
    const int rbase = mtile * MT;
    const int cbase = ntile * NTT;

    const int wm = (wid >> 2) * 64;   // warp row offset
    const int wn = (wid & 3) * 32;    // warp col offset

    // cp.async source/dst mapping: 8 uint4 per thread per tile
    const int lr = tid >> 4;          // 0..15 base row step 16/iter? (u>>4 with u=tid+256j)
    const int lc = tid & 15;          // 16B column chunk

    float acc[4][4][4];
#pragma unroll
    for (int a = 0; a < 4; a++)
#pragma unroll
        for (int b = 0; b < 4; b++)
#pragma unroll
            for (int c = 0; c < 4; c++) acc[a][b][c] = 0.f;

    auto load_chunk = [&](int ch, int buf) {
        const __half* As = g_HA  + (size_t)rbase * KP + ch * KCH;
        const __half* Bs = g_CBH + (size_t)cbase * KP + ch * KCH;
        uint32_t Ad = sb + (buf ? SA1 : SA0);
        uint32_t Bd = sb + (buf ? SB1 : SB0);
#pragma unroll
        for (int j = 0; j < 8; j++) {
            int r = lr + j * 16;
            int sw = (lc * 16) ^ ((r & 7) * 16);
            uint32_t d = r * 256 + sw;
            cp16(Ad + d, As + (size_t)r * KP + lc * 8);
            cp16(Bd + d, Bs + (size_t)r * KP + lc * 8);
        }
        cp_commit();
    };

    load_chunk(0, 0);
    load_chunk(1, 1);

#pragma unroll 1
    for (int ch = 0; ch < NCH; ch++) {
        if (ch == NCH - 1) asm volatile("cp.async.wait_group 0;" ::: "memory");
        else               asm volatile("cp.async.wait_group 1;" ::: "memory");
        __syncthreads();

        const uint32_t Ab = sb + ((ch & 1) ? SA1 : SA0);
        const uint32_t Bb = sb + ((ch & 1) ? SB1 : SB0);

#pragma unroll
        for (int k0 = 0; k0 < 8; k0++) {
            uint32_t af[4][4], bf[2][4];
            {
                int r = (lane & 15);
                int cb16 = k0 * 32 + ((lane >> 4) & 1) * 16;
#pragma unroll
                for (int mi = 0; mi < 4; mi++) {
                    int row = wm + mi * 16 + r;
                    ldsm4(af[mi], Ab + row * 256 + (cb16 ^ ((row & 7) * 16)));
                }
            }
            {
                int nr = ((lane >> 4) & 1) * 8 + (lane & 7);
                int cb16 = k0 * 32 + ((lane >> 3) & 1) * 16;
#pragma unroll
                for (int nj = 0; nj < 2; nj++) {
                    int n = wn + nj * 16 + nr;
                    ldsm4(bf[nj], Bb + n * 256 + (cb16 ^ ((n & 7) * 16)));
                }
            }
#pragma unroll
            for (int mi = 0; mi < 4; mi++)
#pragma unroll
                for (int ni = 0; ni < 4; ni++)
                    mma16816(acc[mi][ni], af[mi], bf[ni >> 1] + (ni & 1) * 2);
        }
        __syncthreads();
        if (ch + 2 < NCH) load_chunk(ch + 2, ch & 1);
    }

    // epilogue: dist = (hsq - 2*dot) + csq, packed argmin
    const int qr = lane >> 2;
    const int qc = lane & 3;
#pragma unroll
    for (int mi = 0; mi < 4; mi++) {
#pragma unroll
        for (int half = 0; half < 2; half++) {
            int rl = wm + mi * 16 + qr + 8 * half;
            float hv = g_hsq[rbase + rl];
            float bv = 3.4e38f;
            int   bi = 0x7fffffff;
#pragma unroll
            for (int ni = 0; ni < 4; ni++) {
#pragma unroll
                for (int e = 0; e < 2; e++) {
                    int cl = wn + ni * 8 + 2 * qc + e;
                    int cg = cbase + cl;
                    float d = acc[mi][ni][half * 2 + e];
                    float dist = __fadd_rn(__fsub_rn(hv, 2.0f * d), __ldg(&g_csq[cg]));
                    if (dist < bv || (dist == bv && cg < bi)) { bv = dist; bi = cg; }
                }
            }
            unsigned long long pk =
                ((unsigned long long)__float_as_uint(bv) << 32) | (unsigned)bi;
#pragma unroll
            for (int off = 1; off <= 2; off <<= 1) {
                unsigned long long o = __shfl_xor_sync(0xffffffffu, pk, off);
                if (o < pk) pk = o;
            }
            if (qc == 0) atomicMin(&sred[rl], pk);
        }
    }
    __syncthreads();
    if (tid < MT) atomicMin(&g_best[rbase + tid], sred[tid]);
}

// k3: zero + one-hot scatter
__global__ void fill_kernel(float* __restrict__ out, int K) {
    int row = blockIdx.x;
    int idx = (int)(g_best[row] & 0xffffffffu);
    float4* o = (float4*)(out + (size_t)row * K);
    int nf4 = K >> 2;
    for (int u = threadIdx.x; u < nf4; u += blockDim.x) {
        int c = u << 2;
        float4 v;
        v.x = (c     == idx) ? 1.f : 0.f;
        v.y = (c + 1 == idx) ? 1.f : 0.f;
        v.z = (c + 2 == idx) ? 1.f : 0.f;
        v.w = (c + 3 == idx) ? 1.f : 0.f;
        o[u] = v;
    }
}

// k4: loss = 1.25 * mean((h - z_q)^2)
__global__ void loss_kernel(const float* __restrict__ h, const float* __restrict__ cb,
                            float* __restrict__ loss_out) {
    int row  = blockIdx.x * 8 + (threadIdx.x >> 5);
    int lane = threadIdx.x & 31;
    int idx  = (int)(g_best[row] & 0xffffffffu);
    const float4* hp = (const float4*)(h  + (size_t)row * HD);
    const float4* cp = (const float4*)(cb + (size_t)idx * HD);
    float s = 0.f;
#pragma unroll
    for (int i = 0; i < 2; i++) {
        float4 a = hp[lane + 32 * i];
        float4 b = cp[lane + 32 * i];
        float dx = a.x - b.x, dy = a.y - b.y, dz = a.z - b.z, dw = a.w - b.w;
        s += dx * dx + dy * dy + dz * dz + dw * dw;
    }
#pragma unroll
    for (int o = 16; o; o >>= 1) s += __shfl_xor_sync(0xffffffffu, s, o);
    if (lane == 0) loss_out[row] = s * (1.25f / 256.0f);
}

extern "C" void kernel_launch(void* const* d_in, const int* in_sizes, int n_in,
                              void* d_out, int out_size) {
    const float* h  = (const float*)d_in[0];
    const float* cb = (const float*)d_in[2];   // d_in[1] = temperature (unused)
    float* out = (float*)d_out;

    int N = in_sizes[0] / HD;   // 8192
    int K = in_sizes[2] / HD;   // 8192

    static int attr_done = 0;
    if (!attr_done) {
        cudaFuncSetAttribute(vq_mma_kernel,
                             cudaFuncAttributeMaxDynamicSharedMemorySize, SMEMSZ);
        attr_done = 1;
    }

    prep_kernel<<<2 * NROWS * HD / TPB, TPB>>>(h, cb);
    sqnorm_kernel<<<(N + K) / 8, TPB>>>(h, cb, N);
    vq_mma_kernel<<<(NROWS / MT) * (KCODES / NTT), TPB, SMEMSZ>>>();
    fill_kernel<<<N, TPB>>>(out, K);
    loss_kernel<<<N / 8, TPB>>>(h, cb, out + (size_t)N * K);
}

// round 11
// speedup vs baseline: 2.2592x; 1.3890x over previous
#include <cuda_runtime.h>
#include <cuda_fp16.h>
#include <cstdint>

#define NROWS 8192
#define KCODES 8192
#define HD 256
#define KP 768           // expanded K: 3 fp16 segments of 256 (h0c0 + h0c1 + h1c0)
#define MT 128           // rows per CTA
#define NTT 256          // codes per CTA
#define KCH 128          // fp16 per K chunk (256 B/row)
#define NCH 6            // 768/128
#define TPB 256

// smem offsets (bytes): per stage A=32KB, B=64KB, double buffered
#define SA0 0
#define SB0 32768
#define SA1 98304
#define SB1 131072
#define SRED 196608
#define SMEMSZ 197632

__device__ __align__(128) __half g_HA[(size_t)NROWS * KP];
__device__ __align__(128) __half g_CBH[(size_t)KCODES * KP];
__device__ float g_hsq[NROWS];
__device__ float g_csq[KCODES];
__device__ unsigned long long g_best[NROWS];

__device__ __forceinline__ uint32_t smem_u32(const void* p) {
    uint32_t a;
    asm("{ .reg .u64 t; cvta.to.shared.u64 t, %1; cvt.u32.u64 %0, t; }"
        : "=r"(a) : "l"(p));
    return a;
}
__device__ __forceinline__ void cp16(uint32_t dst, const void* src) {
    asm volatile("cp.async.cg.shared.global [%0], [%1], 16;"
                 :: "r"(dst), "l"(src) : "memory");
}
__device__ __forceinline__ void cp_commit() {
    asm volatile("cp.async.commit_group;" ::: "memory");
}
__device__ __forceinline__ void ldsm4(uint32_t* r, uint32_t a) {
    asm volatile("ldmatrix.sync.aligned.m8n8.x4.shared.b16 {%0,%1,%2,%3}, [%4];"
                 : "=r"(r[0]), "=r"(r[1]), "=r"(r[2]), "=r"(r[3]) : "r"(a));
}
__device__ __forceinline__ void mma16816(float* c, const uint32_t* a, const uint32_t* b) {
    asm volatile("mma.sync.aligned.m16n8k16.row.col.f32.f16.f16.f32 "
                 "{%0,%1,%2,%3}, {%4,%5,%6,%7}, {%8,%9}, {%0,%1,%2,%3};"
                 : "+f"(c[0]), "+f"(c[1]), "+f"(c[2]), "+f"(c[3])
                 : "r"(a[0]), "r"(a[1]), "r"(a[2]), "r"(a[3]), "r"(b[0]), "r"(b[1]));
}
__device__ __forceinline__ uint32_t pack_h2(float a, float b) {
    __half2 h = __floats2half2_rn(a, b);
    return *(uint32_t*)&h;
}

// k0: fused split-plane build + row norms + g_best init (one warp per row)
__global__ void prep_kernel(const float* __restrict__ h, const float* __restrict__ cb) {
    int row  = blockIdx.x * 8 + (threadIdx.x >> 5);
    int lane = threadIdx.x & 31;
    int which = row >= NROWS;            // 0: h row, 1: codebook row
    int r = which ? row - NROWS : row;
    const float* src = (which ? cb : h) + (size_t)r * HD;
    __half* dst = (which ? g_CBH : g_HA) + (size_t)r * KP;

    float s = 0.f;
#pragma unroll
    for (int i = 0; i < 2; i++) {
        float4 v = *(const float4*)(src + (lane + 32 * i) * 4);
        s += v.x * v.x + v.y * v.y + v.z * v.z + v.w * v.w;
        float f[4] = {v.x, v.y, v.z, v.w};
        float lo[4], hi[4];
#pragma unroll
        for (int j = 0; j < 4; j++) {
            __half p0 = __float2half_rn(f[j]);
            lo[j] = __half2float(p0);
            hi[j] = f[j] - lo[j];
        }
        uint32_t q0[2] = {pack_h2(lo[0], lo[1]), pack_h2(lo[2], lo[3])};
        uint32_t q1[2] = {pack_h2(hi[0], hi[1]), pack_h2(hi[2], hi[3])};
        int e = (lane + 32 * i) * 4;
        // h: [h0, h0, h1]   cb: [c0, c1, c0]
        *(uint2*)(dst + e)       = *(uint2*)q0;
        *(uint2*)(dst + 256 + e) = which ? *(uint2*)q1 : *(uint2*)q0;
        *(uint2*)(dst + 512 + e) = which ? *(uint2*)q0 : *(uint2*)q1;
    }
#pragma unroll
    for (int o = 16; o; o >>= 1) s += __shfl_xor_sync(0xffffffffu, s, o);
    if (lane == 0) { if (which) g_csq[r] = s; else g_hsq[r] = s; }
    if (!which && lane == 1) g_best[r] = ~0ULL;
}

// k1: fp16 HMMA GEMM (K=768, 128x256 tile) + fused dist/argmin epilogue
__global__ void __launch_bounds__(TPB, 1) vq_mma_kernel() {
    extern __shared__ char smem[];
    const uint32_t sb = smem_u32(smem);
    unsigned long long* sred = (unsigned long long*)(smem + SRED);

    const int tid  = threadIdx.x;
    const int wid  = tid >> 5;
    const int lane = tid & 31;

    if (tid < MT) sred[tid] = ~0ULL;

    const int mtile = blockIdx.x >> 5;
    const int ntile = blockIdx.x & 31;
    const int rbase = mtile * MT;
    const int cbase = ntile * NTT;

    const int wm = (wid >> 2) * 64;   // warp row offset (0,64)
    const int wn = (wid & 3) * 64;    // warp col offset (0..192)

    const int lr = tid >> 4;          // 0..15
    const int lc = tid & 15;          // 16B column chunk

    float acc[4][8][4];
#pragma unroll
    for (int a = 0; a < 4; a++)
#pragma unroll
        for (int b = 0; b < 8; b++)
#pragma unroll
            for (int c = 0; c < 4; c++) acc[a][b][c] = 0.f;

    auto load_chunk = [&](int ch, int buf) {
        const __half* As = g_HA  + (size_t)rbase * KP + ch * KCH;
        const __half* Bs = g_CBH + (size_t)cbase * KP + ch * KCH;
        uint32_t Ad = sb + (buf ? SA1 : SA0);
        uint32_t Bd = sb + (buf ? SB1 : SB0);
        int sw = (lc * 16) ^ ((lr & 7) * 16);
#pragma unroll
        for (int j = 0; j < 8; j++) {
            int r = lr + j * 16;
            cp16(Ad + r * 256 + sw, As + (size_t)r * KP + lc * 8);
        }
#pragma unroll
        for (int j = 0; j < 16; j++) {
            int r = lr + j * 16;
            cp16(Bd + r * 256 + sw, Bs + (size_t)r * KP + lc * 8);
        }
        cp_commit();
    };

    load_chunk(0, 0);
    load_chunk(1, 1);

#pragma unroll 1
    for (int ch = 0; ch < NCH; ch++) {
        if (ch == NCH - 1) asm volatile("cp.async.wait_group 0;" ::: "memory");
        else               asm volatile("cp.async.wait_group 1;" ::: "memory");
        __syncthreads();

        const uint32_t Ab = sb + ((ch & 1) ? SA1 : SA0);
        const uint32_t Bb = sb + ((ch & 1) ? SB1 : SB0);

#pragma unroll
        for (int k0 = 0; k0 < 8; k0++) {
            uint32_t af[4][4], bf[4][4];
            {
                int r = lane & 15;
                int cb16 = k0 * 32 + ((lane >> 4) & 1) * 16;
#pragma unroll
                for (int mi = 0; mi < 4; mi++) {
                    int row = wm + mi * 16 + r;
                    ldsm4(af[mi], Ab + row * 256 + (cb16 ^ ((row & 7) * 16)));
                }
            }
            {
                int nr = ((lane >> 4) & 1) * 8 + (lane & 7);
                int cb16 = k0 * 32 + ((lane >> 3) & 1) * 16;
#pragma unroll
                for (int nj = 0; nj < 4; nj++) {
                    int n = wn + nj * 16 + nr;
                    ldsm4(bf[nj], Bb + n * 256 + (cb16 ^ ((n & 7) * 16)));
                }
            }
#pragma unroll
            for (int mi = 0; mi < 4; mi++)
#pragma unroll
                for (int ni = 0; ni < 8; ni++)
                    mma16816(acc[mi][ni], af[mi], bf[ni >> 1] + (ni & 1) * 2);
        }
        __syncthreads();
        if (ch + 2 < NCH) load_chunk(ch + 2, ch & 1);
    }

    // epilogue: dist = (hsq - 2*dot) + csq, packed argmin
    const int qr = lane >> 2;
    const int qc = lane & 3;
#pragma unroll
    for (int mi = 0; mi < 4; mi++) {
#pragma unroll
        for (int half = 0; half < 2; half++) {
            int rl = wm + mi * 16 + qr + 8 * half;
            float hv = g_hsq[rbase + rl];
            float bv = 3.4e38f;
            int   bi = 0x7fffffff;
#pragma unroll
            for (int ni = 0; ni < 8; ni++) {
#pragma unroll
                for (int e = 0; e < 2; e++) {
                    int cg = cbase + wn + ni * 8 + 2 * qc + e;
                    float d = acc[mi][ni][half * 2 + e];
                    float dist = __fadd_rn(__fsub_rn(hv, 2.0f * d), __ldg(&g_csq[cg]));
                    if (dist < bv || (dist == bv && cg < bi)) { bv = dist; bi = cg; }
                }
            }
            unsigned long long pk =
                ((unsigned long long)__float_as_uint(bv) << 32) | (unsigned)bi;
#pragma unroll
            for (int off = 1; off <= 2; off <<= 1) {
                unsigned long long o = __shfl_xor_sync(0xffffffffu, pk, off);
                if (o < pk) pk = o;
            }
            if (qc == 0) atomicMin(&sred[rl], pk);
        }
    }
    __syncthreads();
    if (tid < MT) atomicMin(&g_best[rbase + tid], sred[tid]);
}

// k2: zero + one-hot scatter
__global__ void fill_kernel(float* __restrict__ out, int K) {
    int row = blockIdx.x;
    int idx = (int)(g_best[row] & 0xffffffffu);
    float4* o = (float4*)(out + (size_t)row * K);
    int nf4 = K >> 2;
    for (int u = threadIdx.x; u < nf4; u += blockDim.x) {
        int c = u << 2;
        float4 v;
        v.x = (c     == idx) ? 1.f : 0.f;
        v.y = (c + 1 == idx) ? 1.f : 0.f;
        v.z = (c + 2 == idx) ? 1.f : 0.f;
        v.w = (c + 3 == idx) ? 1.f : 0.f;
        o[u] = v;
    }
}

// k3: loss = 1.25 * mean((h - z_q)^2)
__global__ void loss_kernel(const float* __restrict__ h, const float* __restrict__ cb,
                            float* __restrict__ loss_out) {
    int row  = blockIdx.x * 8 + (threadIdx.x >> 5);
    int lane = threadIdx.x & 31;
    int idx  = (int)(g_best[row] & 0xffffffffu);
    const float4* hp = (const float4*)(h  + (size_t)row * HD);
    const float4* cp = (const float4*)(cb + (size_t)idx * HD);
    float s = 0.f;
#pragma unroll
    for (int i = 0; i < 2; i++) {
        float4 a = hp[lane + 32 * i];
        float4 b = cp[lane + 32 * i];
        float dx = a.x - b.x, dy = a.y - b.y, dz = a.z - b.z, dw = a.w - b.w;
        s += dx * dx + dy * dy + dz * dz + dw * dw;
    }
#pragma unroll
    for (int o = 16; o; o >>= 1) s += __shfl_xor_sync(0xffffffffu, s, o);
    if (lane == 0) loss_out[row] = s * (1.25f / 256.0f);
}

extern "C" void kernel_launch(void* const* d_in, const int* in_sizes, int n_in,
                              void* d_out, int out_size) {
    const float* h  = (const float*)d_in[0];
    const float* cb = (const float*)d_in[2];   // d_in[1] = temperature (unused)
    float* out = (float*)d_out;

    int N = in_sizes[0] / HD;   // 8192
    int K = in_sizes[2] / HD;   // 8192

    static int attr_done = 0;
    if (!attr_done) {
        cudaFuncSetAttribute(vq_mma_kernel,
                             cudaFuncAttributeMaxDynamicSharedMemorySize, SMEMSZ);
        attr_done = 1;
    }

    prep_kernel<<<(N + K) / 8, TPB>>>(h, cb);
    vq_mma_kernel<<<(NROWS / MT) * (KCODES / NTT), TPB, SMEMSZ>>>();
    fill_kernel<<<N, TPB>>>(out, K);
    loss_kernel<<<N / 8, TPB>>>(h, cb, out + (size_t)N * K);
}

// round 12
// speedup vs baseline: 2.5578x; 1.1322x over previous
#include <cuda_runtime.h>
#include <cuda_fp16.h>
#include <cstdint>

#define NROWS 8192
#define KCODES 8192
#define HD 256
#define KP 768           // expanded K: 3 fp16 segments of 256 (h0c0 + h0c1 + h1c0)
#define MT 128           // rows per CTA
#define NTT 128          // codes per CTA
#define KCH 64           // fp16 per K chunk (128 B/row)
#define NCH 12           // 768/64
#define TPB 256

// smem offsets (bytes): per stage A=16KB, B=16KB, double buffered
#define SA0 0
#define SB0 16384
#define SA1 32768
#define SB1 49152
#define SRED 65536
#define SMEMSZ 66560

__device__ __align__(128) __half g_HA[(size_t)NROWS * KP];
__device__ __align__(128) __half g_CBH[(size_t)KCODES * KP];
__device__ float g_hsq[NROWS];
__device__ float g_csq[KCODES];
__device__ unsigned long long g_best[NROWS];

__device__ __forceinline__ uint32_t smem_u32(const void* p) {
    uint32_t a;
    asm("{ .reg .u64 t; cvta.to.shared.u64 t, %1; cvt.u32.u64 %0, t; }"
        : "=r"(a) : "l"(p));
    return a;
}
__device__ __forceinline__ void cp16(uint32_t dst, const void* src) {
    asm volatile("cp.async.cg.shared.global [%0], [%1], 16;"
                 :: "r"(dst), "l"(src) : "memory");
}
__device__ __forceinline__ void cp_commit() {
    asm volatile("cp.async.commit_group;" ::: "memory");
}
__device__ __forceinline__ void ldsm4(uint32_t* r, uint32_t a) {
    asm volatile("ldmatrix.sync.aligned.m8n8.x4.shared.b16 {%0,%1,%2,%3}, [%4];"
                 : "=r"(r[0]), "=r"(r[1]), "=r"(r[2]), "=r"(r[3]) : "r"(a));
}
__device__ __forceinline__ void mma16816(float* c, const uint32_t* a, const uint32_t* b) {
    asm volatile("mma.sync.aligned.m16n8k16.row.col.f32.f16.f16.f32 "
                 "{%0,%1,%2,%3}, {%4,%5,%6,%7}, {%8,%9}, {%0,%1,%2,%3};"
                 : "+f"(c[0]), "+f"(c[1]), "+f"(c[2]), "+f"(c[3])
                 : "r"(a[0]), "r"(a[1]), "r"(a[2]), "r"(a[3]), "r"(b[0]), "r"(b[1]));
}
__device__ __forceinline__ uint32_t pack_h2(float a, float b) {
    __half2 h = __floats2half2_rn(a, b);
    return *(uint32_t*)&h;
}

// k0: fused split-plane build + row norms + g_best init (one warp per row)
__global__ void prep_kernel(const float* __restrict__ h, const float* __restrict__ cb) {
    int row  = blockIdx.x * 8 + (threadIdx.x >> 5);
    int lane = threadIdx.x & 31;
    int which = row >= NROWS;            // 0: h row, 1: codebook row
    int r = which ? row - NROWS : row;
    const float* src = (which ? cb : h) + (size_t)r * HD;
    __half* dst = (which ? g_CBH : g_HA) + (size_t)r * KP;

    float s = 0.f;
#pragma unroll
    for (int i = 0; i < 2; i++) {
        float4 v = *(const float4*)(src + (lane + 32 * i) * 4);
        s += v.x * v.x + v.y * v.y + v.z * v.z + v.w * v.w;
        float f[4] = {v.x, v.y, v.z, v.w};
        float lo[4], hi[4];
#pragma unroll
        for (int j = 0; j < 4; j++) {
            __half p0 = __float2half_rn(f[j]);
            lo[j] = __half2float(p0);
            hi[j] = f[j] - lo[j];
        }
        uint32_t q0[2] = {pack_h2(lo[0], lo[1]), pack_h2(lo[2], lo[3])};
        uint32_t q1[2] = {pack_h2(hi[0], hi[1]), pack_h2(hi[2], hi[3])};
        int e = (lane + 32 * i) * 4;
        // h: [h0, h0, h1]   cb: [c0, c1, c0]
        *(uint2*)(dst + e)       = *(uint2*)q0;
        *(uint2*)(dst + 256 + e) = which ? *(uint2*)q1 : *(uint2*)q0;
        *(uint2*)(dst + 512 + e) = which ? *(uint2*)q0 : *(uint2*)q1;
    }
#pragma unroll
    for (int o = 16; o; o >>= 1) s += __shfl_xor_sync(0xffffffffu, s, o);
    if (lane == 0) { if (which) g_csq[r] = s; else g_hsq[r] = s; }
    if (!which && lane == 1) g_best[r] = ~0ULL;
}

// k1: fp16 HMMA GEMM (K=768, 128x128 tile, 2 CTAs/SM) + fused dist/argmin
__global__ void __launch_bounds__(TPB, 2) vq_mma_kernel() {
    extern __shared__ char smem[];
    const uint32_t sb = smem_u32(smem);
    unsigned long long* sred = (unsigned long long*)(smem + SRED);

    const int tid  = threadIdx.x;
    const int wid  = tid >> 5;
    const int lane = tid & 31;

    if (tid < MT) sred[tid] = ~0ULL;

    // panel-swizzled coords: 8-wide n panels for L2 reuse
    const int bid   = blockIdx.x;
    const int panel = bid >> 9;               // 0..7
    const int mtile = (bid >> 3) & 63;        // 0..63
    const int ntile = (panel << 3) | (bid & 7);
    const int rbase = mtile * MT;
    const int cbase = ntile * NTT;

    const int wm = (wid >> 2) * 64;   // warp row offset (0,64)
    const int wn = (wid & 3) * 32;    // warp col offset (0..96)

    float acc[4][4][4];
#pragma unroll
    for (int a = 0; a < 4; a++)
#pragma unroll
        for (int b = 0; b < 4; b++)
#pragma unroll
            for (int c = 0; c < 4; c++) acc[a][b][c] = 0.f;

    auto load_chunk = [&](int ch, int buf) {
        const __half* As = g_HA  + (size_t)rbase * KP + ch * KCH;
        const __half* Bs = g_CBH + (size_t)cbase * KP + ch * KCH;
        uint32_t Ad = sb + (buf ? SA1 : SA0);
        uint32_t Bd = sb + (buf ? SB1 : SB0);
#pragma unroll
        for (int j = 0; j < 4; j++) {
            int u = tid + j * TPB;            // 0..1023
            int r = u >> 3, c = u & 7;
            int d = r * 128 + ((c * 16) ^ ((r & 7) * 16));
            cp16(Ad + d, As + (size_t)r * KP + c * 8);
            cp16(Bd + d, Bs + (size_t)r * KP + c * 8);
        }
        cp_commit();
    };

    load_chunk(0, 0);
    load_chunk(1, 1);

#pragma unroll 1
    for (int ch = 0; ch < NCH; ch++) {
        if (ch == NCH - 1) asm volatile("cp.async.wait_group 0;" ::: "memory");
        else               asm volatile("cp.async.wait_group 1;" ::: "memory");
        __syncthreads();

        const uint32_t Ab = sb + ((ch & 1) ? SA1 : SA0);
        const uint32_t Bb = sb + ((ch & 1) ? SB1 : SB0);

#pragma unroll
        for (int k0 = 0; k0 < 4; k0++) {
            uint32_t af[4][4], bf[2][4];
            {
                int r = lane & 15;
                int cb16 = k0 * 32 + ((lane >> 4) & 1) * 16;
#pragma unroll
                for (int mi = 0; mi < 4; mi++) {
                    int row = wm + mi * 16 + r;
                    ldsm4(af[mi], Ab + row * 128 + (cb16 ^ ((row & 7) * 16)));
                }
            }
            {
                int nr = ((lane >> 4) & 1) * 8 + (lane & 7);
                int cb16 = k0 * 32 + ((lane >> 3) & 1) * 16;
#pragma unroll
                for (int nj = 0; nj < 2; nj++) {
                    int n = wn + nj * 16 + nr;
                    ldsm4(bf[nj], Bb + n * 128 + (cb16 ^ ((n & 7) * 16)));
                }
            }
#pragma unroll
            for (int mi = 0; mi < 4; mi++)
#pragma unroll
                for (int ni = 0; ni < 4; ni++)
                    mma16816(acc[mi][ni], af[mi], bf[ni >> 1] + (ni & 1) * 2);
        }
        __syncthreads();
        if (ch + 2 < NCH) load_chunk(ch + 2, ch & 1);
    }

    // epilogue: dist = (hsq - 2*dot) + csq, packed argmin
    const int qr = lane >> 2;
    const int qc = lane & 3;
#pragma unroll
    for (int mi = 0; mi < 4; mi++) {
#pragma unroll
        for (int half = 0; half < 2; half++) {
            int rl = wm + mi * 16 + qr + 8 * half;
            float hv = g_hsq[rbase + rl];
            float bv = 3.4e38f;
            int   bi = 0x7fffffff;
#pragma unroll
            for (int ni = 0; ni < 4; ni++) {
#pragma unroll
                for (int e = 0; e < 2; e++) {
                    int cg = cbase + wn + ni * 8 + 2 * qc + e;
                    float d = acc[mi][ni][half * 2 + e];
                    float dist = __fadd_rn(__fsub_rn(hv, 2.0f * d), __ldg(&g_csq[cg]));
                    if (dist < bv || (dist == bv && cg < bi)) { bv = dist; bi = cg; }
                }
            }
            unsigned long long pk =
                ((unsigned long long)__float_as_uint(bv) << 32) | (unsigned)bi;
#pragma unroll
            for (int off = 1; off <= 2; off <<= 1) {
                unsigned long long o = __shfl_xor_sync(0xffffffffu, pk, off);
                if (o < pk) pk = o;
            }
            if (qc == 0) atomicMin(&sred[rl], pk);
        }
    }
    __syncthreads();
    if (tid < MT) atomicMin(&g_best[rbase + tid], sred[tid]);
}

// k2: zero + one-hot scatter, with loss fused into warp 0
__global__ void fill_kernel(const float* __restrict__ h, const float* __restrict__ cb,
                            float* __restrict__ out, int K, int N) {
    int row = blockIdx.x;
    int idx = (int)(g_best[row] & 0xffffffffu);
    int tid = threadIdx.x;

    if (tid < 32) {  // warp 0: loss = 1.25 * mean((h - z_q)^2)
        const float4* hp = (const float4*)(h  + (size_t)row * HD);
        const float4* cp = (const float4*)(cb + (size_t)idx * HD);
        float s = 0.f;
#pragma unroll
        for (int i = 0; i < 2; i++) {
            float4 a = hp[tid + 32 * i];
            float4 b = cp[tid + 32 * i];
            float dx = a.x - b.x, dy = a.y - b.y, dz = a.z - b.z, dw = a.w - b.w;
            s += dx * dx + dy * dy + dz * dz + dw * dw;
        }
#pragma unroll
        for (int o = 16; o; o >>= 1) s += __shfl_xor_sync(0xffffffffu, s, o);
        if (tid == 0) out[(size_t)N * K + row] = s * (1.25f / 256.0f);
    }

    float4* o = (float4*)(out + (size_t)row * K);
    int nf4 = K >> 2;
    for (int u = tid; u < nf4; u += blockDim.x) {
        int c = u << 2;
        float4 v;
        v.x = (c     == idx) ? 1.f : 0.f;
        v.y = (c + 1 == idx) ? 1.f : 0.f;
        v.z = (c + 2 == idx) ? 1.f : 0.f;
        v.w = (c + 3 == idx) ? 1.f : 0.f;
        __stcs(o + u, v);
    }
}

extern "C" void kernel_launch(void* const* d_in, const int* in_sizes, int n_in,
                              void* d_out, int out_size) {
    const float* h  = (const float*)d_in[0];
    const float* cb = (const float*)d_in[2];   // d_in[1] = temperature (unused)
    float* out = (float*)d_out;

    int N = in_sizes[0] / HD;   // 8192
    int K = in_sizes[2] / HD;   // 8192

    static int attr_done = 0;
    if (!attr_done) {
        cudaFuncSetAttribute(vq_mma_kernel,
                             cudaFuncAttributeMaxDynamicSharedMemorySize, SMEMSZ);
        attr_done = 1;
    }

    prep_kernel<<<(N + K) / 8, TPB>>>(h, cb);
    vq_mma_kernel<<<(NROWS / MT) * (KCODES / NTT), TPB, SMEMSZ>>>();
    fill_kernel<<<N, TPB>>>(h, cb, out, K, N);
}